// round 1
// baseline (speedup 1.0000x reference)
#include <cuda_runtime.h>

// ---------------------------------------------------------------------------
// SparseNeuralNetwork: 256 independent 1->16->8->1 micro-MLPs.
//   out[b,o] = b2[o] + sum_i MLP_{i,o}(x[b,i])
// Layer0 row r: y0[r] = relu(W0[r, r>>8] * x[r>>8] + b0[r])
// Layer1 row r: y1[r] = relu(sum_k W1[r, (r>>3)*16+k] * y0[(r>>3)*16+k] + b1[r])
// Layer2:       out[o] = sum_{r:(r>>3)%16==o} W2[o, r] * y1[r] + b2[o]
// ---------------------------------------------------------------------------

// Compacted (nonzero-only) weights. Scratch via __device__ globals (no allocs).
__device__ float g_w0[4096];
__device__ float g_w1[32768];
__device__ float g_w2[2048];

__global__ void gather_kernel(const float* __restrict__ W0,
                              const float* __restrict__ W1,
                              const float* __restrict__ W2) {
    int t = blockIdx.x * blockDim.x + threadIdx.x;
    if (t < 4096) g_w0[t] = W0[t * 16 + (t >> 8)];
    if (t < 2048) g_w2[t] = W2[((t >> 3) & 15) * 2048 + t];
    if (t < 32768) {
        int r = t >> 4;
        int k = t & 15;
        g_w1[t] = W1[r * 4096 + (r >> 3) * 16 + k];
    }
}

// Shared memory layout (floats):
//   sw1   [32768]  layer1 weights, row-major 16 per y1-unit
//   sw0   [ 4096]  layer0 weights
//   sb0   [ 4096]  layer0 bias
//   sb1   [ 2048]  layer1 bias
//   sw2   [ 2048]  layer2 weights (indexed by y1 row)
//   spart [ 8192]  partials: [(i*16+o)*32 + lane]  (16 i * 16 o * 32 samples)
constexpr int SMEM_FLOATS = 32768 + 4096 + 4096 + 2048 + 2048 + 8192;
constexpr int SMEM_BYTES  = SMEM_FLOATS * 4;   // 212992 B

__global__ __launch_bounds__(512, 1)
void mlp_kernel(const float* __restrict__ x,
                const float* __restrict__ b0,
                const float* __restrict__ b1,
                const float* __restrict__ b2,
                float* __restrict__ out,
                int n) {
    extern __shared__ float smem[];
    float* sw1   = smem;
    float* sw0   = sw1 + 32768;
    float* sb0   = sw0 + 4096;
    float* sb1   = sb0 + 4096;
    float* sw2   = sb1 + 2048;
    float* spart = sw2 + 2048;

    const int tid  = threadIdx.x;
    const int warp = tid >> 5;   // warp == input index i during compute phase
    const int lane = tid & 31;   // lane == local sample index

    // ---- Stage all compacted weights/biases into shared memory (float4) ----
    {
        const float4* s;
        float4* d;
        s = (const float4*)g_w1; d = (float4*)sw1;
        for (int idx = tid; idx < 32768 / 4; idx += 512) d[idx] = s[idx];
        s = (const float4*)g_w0; d = (float4*)sw0;
        for (int idx = tid; idx < 4096 / 4; idx += 512) d[idx] = s[idx];
        s = (const float4*)b0;   d = (float4*)sb0;
        for (int idx = tid; idx < 4096 / 4; idx += 512) d[idx] = s[idx];
        s = (const float4*)b1;   d = (float4*)sb1;
        for (int idx = tid; idx < 2048 / 4; idx += 512) d[idx] = s[idx];
        s = (const float4*)g_w2; d = (float4*)sw2;
        for (int idx = tid; idx < 2048 / 4; idx += 512) d[idx] = s[idx];
    }
    __syncthreads();

    const int i = warp;
    const int chunk_base = blockIdx.x * 64;   // 64 samples per block

    #pragma unroll 1
    for (int half = 0; half < 2; ++half) {
        const int s_idx = chunk_base + half * 32 + lane;
        const float xv = (s_idx < n) ? x[s_idx * 16 + i] : 0.0f;

        // ---- compute partial contribution of input i to each output o ----
        #pragma unroll 1
        for (int o = 0; o < 16; ++o) {
            const int base0 = (i << 8) + (o << 4);   // i*256 + o*16
            float y0[16];
            {
                const float4* a4 = (const float4*)(sw0 + base0);
                const float4* c4 = (const float4*)(sb0 + base0);
                #pragma unroll
                for (int q = 0; q < 4; ++q) {
                    float4 a = a4[q], c = c4[q];
                    y0[4 * q + 0] = fmaxf(fmaf(a.x, xv, c.x), 0.0f);
                    y0[4 * q + 1] = fmaxf(fmaf(a.y, xv, c.y), 0.0f);
                    y0[4 * q + 2] = fmaxf(fmaf(a.z, xv, c.z), 0.0f);
                    y0[4 * q + 3] = fmaxf(fmaf(a.w, xv, c.w), 0.0f);
                }
            }

            const int g8 = ((i << 4) + o) << 3;      // (i*16+o)*8
            float p = 0.0f;
            #pragma unroll
            for (int j = 0; j < 8; ++j) {
                const float4* w4 = (const float4*)(sw1 + ((g8 + j) << 4));
                float acc = sb1[g8 + j];
                #pragma unroll
                for (int q = 0; q < 4; ++q) {
                    float4 w = w4[q];
                    acc = fmaf(w.x, y0[4 * q + 0], acc);
                    acc = fmaf(w.y, y0[4 * q + 1], acc);
                    acc = fmaf(w.z, y0[4 * q + 2], acc);
                    acc = fmaf(w.w, y0[4 * q + 3], acc);
                }
                p = fmaf(sw2[g8 + j], fmaxf(acc, 0.0f), p);
            }
            // conflict-free: lanes write consecutive words
            spart[(((i << 4) + o) << 5) + lane] = p;
        }
        __syncthreads();

        // ---- reduce over i: warp == output o, lane == sample ----
        {
            const int o = warp;
            float acc = 0.0f;
            #pragma unroll
            for (int ii = 0; ii < 16; ++ii)
                acc += spart[(((ii << 4) + o) << 5) + lane];
            const int sg = chunk_base + half * 32 + lane;
            if (sg < n)
                out[sg * 16 + o] = acc + __ldg(&b2[o]);
        }
        __syncthreads();
    }
}

extern "C" void kernel_launch(void* const* d_in, const int* in_sizes, int n_in,
                              void* d_out, int out_size) {
    // Map inputs by element count (all distinct for this problem).
    const float *x = nullptr, *W0 = nullptr, *b0 = nullptr, *W1 = nullptr;
    const float *b1 = nullptr, *W2 = nullptr, *b2 = nullptr;
    for (int idx = 0; idx < n_in; ++idx) {
        switch (in_sizes[idx]) {
            case 131072:  x  = (const float*)d_in[idx]; break;   // [8192,16]
            case 65536:   W0 = (const float*)d_in[idx]; break;   // [4096,16]
            case 4096:    b0 = (const float*)d_in[idx]; break;
            case 8388608: W1 = (const float*)d_in[idx]; break;   // [2048,4096]
            case 2048:    b1 = (const float*)d_in[idx]; break;
            case 32768:   W2 = (const float*)d_in[idx]; break;   // [16,2048]
            case 16:      b2 = (const float*)d_in[idx]; break;
            default: break;
        }
    }

    const int n = out_size / 16;   // number of samples

    gather_kernel<<<128, 256>>>(W0, W1, W2);

    cudaFuncSetAttribute(mlp_kernel,
                         cudaFuncAttributeMaxDynamicSharedMemorySize, SMEM_BYTES);
    const int blocks = (n + 63) / 64;
    mlp_kernel<<<blocks, 512, SMEM_BYTES>>>(x, b0, b1, b2, (float*)d_out, n);
}

// round 2
// speedup vs baseline: 1.3688x; 1.3688x over previous
#include <cuda_runtime.h>

// ---------------------------------------------------------------------------
// SparseNeuralNetwork: 256 independent 1->16->8->1 micro-MLPs.
//   out[b,o] = b2[o] + sum_i MLP_{i,o}(x[b,i])
// Strategy: compact nonzero weights -> smem; warp = output o, lane = sample
// pair; packed fp32 (fma.rn.f32x2) over adjacent hidden units (k-pairs) so
// packed weight operands come straight from LDS.128 register pairs.
// ---------------------------------------------------------------------------

typedef unsigned long long ull;

__device__ float g_w0[4096];
__device__ float g_w1[32768];
__device__ float g_w2[2048];

__global__ void gather_kernel(const float* __restrict__ W0,
                              const float* __restrict__ W1,
                              const float* __restrict__ W2) {
    int t = blockIdx.x * blockDim.x + threadIdx.x;
    if (t < 4096) g_w0[t] = W0[t * 16 + (t >> 8)];
    if (t < 2048) g_w2[t] = W2[((t >> 3) & 15) * 2048 + t];
    if (t < 32768) {
        int r = t >> 4;
        int k = t & 15;
        g_w1[t] = W1[r * 4096 + (r >> 3) * 16 + k];
    }
}

// ---- packed f32x2 helpers --------------------------------------------------
__device__ __forceinline__ ull pk2(float lo, float hi) {
    ull r;
    asm("mov.b64 %0, {%1, %2};" : "=l"(r) : "f"(lo), "f"(hi));
    return r;
}
__device__ __forceinline__ void up2(ull v, float& lo, float& hi) {
    asm("mov.b64 {%0, %1}, %2;" : "=f"(lo), "=f"(hi) : "l"(v));
}
__device__ __forceinline__ ull fma2(ull a, ull b, ull c) {
    ull d;
    asm("fma.rn.f32x2 %0, %1, %2, %3;" : "=l"(d) : "l"(a), "l"(b), "l"(c));
    return d;
}
__device__ __forceinline__ ull relu2(ull v) {
    float a, b;
    up2(v, a, b);
    a = fmaxf(a, 0.0f);
    b = fmaxf(b, 0.0f);
    return pk2(a, b);
}

// Shared memory layout (floats):
//   sw1 [32768]  layer1 weights, row-major (16 per y1-unit) -- natural k-pairs
//   sw0 [ 4096]  layer0 weights
//   sb0 [ 4096]  layer0 bias
//   sb1 [ 2048]  layer1 bias
//   sw2 [ 2048]  layer2 weights (indexed by y1 row)
//   sx  [ 1056]  x chunk transposed [16][66] (pad 66 for bank-conflict-free)
constexpr int SMEM_FLOATS = 32768 + 4096 + 4096 + 2048 + 2048 + 1056;
constexpr int SMEM_BYTES  = SMEM_FLOATS * 4;   // 184448 B

__global__ __launch_bounds__(512, 1)
void mlp_kernel(const float* __restrict__ x,
                const float* __restrict__ b0,
                const float* __restrict__ b1,
                const float* __restrict__ b2,
                float* __restrict__ out,
                int n) {
    extern __shared__ float smem[];
    float* sw1 = smem;
    float* sw0 = sw1 + 32768;
    float* sb0 = sw0 + 4096;
    float* sb1 = sb0 + 4096;
    float* sw2 = sb1 + 2048;
    float* sx  = sw2 + 2048;

    const int tid  = threadIdx.x;
    const int o    = tid >> 5;   // warp index = output neuron
    const int lane = tid & 31;   // lane = sample-pair index

    // ---- Stage compacted weights/biases into shared memory (float4) -------
    {
        const float4* s;
        float4* d;
        s = (const float4*)g_w1; d = (float4*)sw1;
        for (int idx = tid; idx < 32768 / 4; idx += 512) d[idx] = s[idx];
        s = (const float4*)g_w0; d = (float4*)sw0;
        for (int idx = tid; idx < 4096 / 4; idx += 512) d[idx] = s[idx];
        s = (const float4*)b0;   d = (float4*)sb0;
        for (int idx = tid; idx < 4096 / 4; idx += 512) d[idx] = s[idx];
        s = (const float4*)b1;   d = (float4*)sb1;
        for (int idx = tid; idx < 2048 / 4; idx += 512) d[idx] = s[idx];
        s = (const float4*)g_w2; d = (float4*)sw2;
        for (int idx = tid; idx < 2048 / 4; idx += 512) d[idx] = s[idx];
    }

    // ---- Stage x chunk transposed: sx[i*66 + s] = x[(base+s)*16 + i] -------
    const int base = blockIdx.x * 64;
    for (int e = tid; e < 1024; e += 512) {
        int s = e >> 4, i = e & 15;
        float v = (base + s < n) ? x[(base + s) * 16 + i] : 0.0f;
        sx[i * 66 + s] = v;
    }
    __syncthreads();

    float outl = 0.0f, outh = 0.0f;   // per-sample output accumulators

    #pragma unroll 1
    for (int i = 0; i < 16; ++i) {
        const float xl = sx[i * 66 + 2 * lane];
        const float xh = sx[i * 66 + 2 * lane + 1];
        const ull xpl = pk2(xl, xl);
        const ull xph = pk2(xh, xh);

        const int base0 = (i << 8) + (o << 4);   // i*256 + o*16
        const int g8    = base0 >> 1;            // (i*16+o)*8

        // ---- layer 0: 16 units as 8 k-packs, both samples -----------------
        ull y0a[8], y0b[8];   // sample0 / sample1, pack = (unit 2k, 2k+1)
        {
            const float4* w4 = (const float4*)(sw0 + base0);
            const float4* c4 = (const float4*)(sb0 + base0);
            #pragma unroll
            for (int q = 0; q < 4; ++q) {
                float4 w = w4[q], c = c4[q];
                ull wp0 = pk2(w.x, w.y), wp1 = pk2(w.z, w.w);
                ull cp0 = pk2(c.x, c.y), cp1 = pk2(c.z, c.w);
                y0a[2 * q + 0] = relu2(fma2(wp0, xpl, cp0));
                y0a[2 * q + 1] = relu2(fma2(wp1, xpl, cp1));
                y0b[2 * q + 0] = relu2(fma2(wp0, xph, cp0));
                y0b[2 * q + 1] = relu2(fma2(wp1, xph, cp1));
            }
        }

        // preload layer1 biases + layer2 weights for the 8 y1 units ---------
        float b1r[8], w2r[8];
        {
            const float4* bb = (const float4*)(sb1 + g8);
            const float4* ww = (const float4*)(sw2 + g8);
            float4 t0 = bb[0], t1 = bb[1];
            b1r[0] = t0.x; b1r[1] = t0.y; b1r[2] = t0.z; b1r[3] = t0.w;
            b1r[4] = t1.x; b1r[5] = t1.y; b1r[6] = t1.z; b1r[7] = t1.w;
            t0 = ww[0]; t1 = ww[1];
            w2r[0] = t0.x; w2r[1] = t0.y; w2r[2] = t0.z; w2r[3] = t0.w;
            w2r[4] = t1.x; w2r[5] = t1.y; w2r[6] = t1.z; w2r[7] = t1.w;
        }

        // ---- layer 1 (+ relu + layer 2 fold), 8 y1 units ------------------
        #pragma unroll
        for (int j = 0; j < 8; ++j) {
            const float4* r4 = (const float4*)(sw1 + ((g8 + j) << 4));
            float4 r0 = r4[0], r1 = r4[1], r2 = r4[2], r3 = r4[3];
            ull wk0 = pk2(r0.x, r0.y), wk1 = pk2(r0.z, r0.w);
            ull wk2 = pk2(r1.x, r1.y), wk3 = pk2(r1.z, r1.w);
            ull wk4 = pk2(r2.x, r2.y), wk5 = pk2(r2.z, r2.w);
            ull wk6 = pk2(r3.x, r3.y), wk7 = pk2(r3.z, r3.w);

            // sample 0
            {
                ull acc = pk2(b1r[j], 0.0f);
                acc = fma2(wk0, y0a[0], acc);
                acc = fma2(wk1, y0a[1], acc);
                acc = fma2(wk2, y0a[2], acc);
                acc = fma2(wk3, y0a[3], acc);
                acc = fma2(wk4, y0a[4], acc);
                acc = fma2(wk5, y0a[5], acc);
                acc = fma2(wk6, y0a[6], acc);
                acc = fma2(wk7, y0a[7], acc);
                float al, ah;
                up2(acc, al, ah);
                outl = fmaf(w2r[j], fmaxf(al + ah, 0.0f), outl);
            }
            // sample 1
            {
                ull acc = pk2(b1r[j], 0.0f);
                acc = fma2(wk0, y0b[0], acc);
                acc = fma2(wk1, y0b[1], acc);
                acc = fma2(wk2, y0b[2], acc);
                acc = fma2(wk3, y0b[3], acc);
                acc = fma2(wk4, y0b[4], acc);
                acc = fma2(wk5, y0b[5], acc);
                acc = fma2(wk6, y0b[6], acc);
                acc = fma2(wk7, y0b[7], acc);
                float al, ah;
                up2(acc, al, ah);
                outh = fmaf(w2r[j], fmaxf(al + ah, 0.0f), outh);
            }
        }
    }

    // ---- write outputs (no cross-thread reduction needed) ------------------
    const float bb = __ldg(&b2[o]);
    const int s0 = base + 2 * lane;
    const int s1 = s0 + 1;
    if (s0 < n) out[s0 * 16 + o] = outl + bb;
    if (s1 < n) out[s1 * 16 + o] = outh + bb;
}

extern "C" void kernel_launch(void* const* d_in, const int* in_sizes, int n_in,
                              void* d_out, int out_size) {
    const float *x = nullptr, *W0 = nullptr, *b0 = nullptr, *W1 = nullptr;
    const float *b1 = nullptr, *W2 = nullptr, *b2 = nullptr;
    for (int idx = 0; idx < n_in; ++idx) {
        switch (in_sizes[idx]) {
            case 131072:  x  = (const float*)d_in[idx]; break;   // [8192,16]
            case 65536:   W0 = (const float*)d_in[idx]; break;   // [4096,16]
            case 4096:    b0 = (const float*)d_in[idx]; break;
            case 8388608: W1 = (const float*)d_in[idx]; break;   // [2048,4096]
            case 2048:    b1 = (const float*)d_in[idx]; break;
            case 32768:   W2 = (const float*)d_in[idx]; break;   // [16,2048]
            case 16:      b2 = (const float*)d_in[idx]; break;
            default: break;
        }
    }

    const int n = out_size / 16;

    gather_kernel<<<128, 256>>>(W0, W1, W2);

    cudaFuncSetAttribute(mlp_kernel,
                         cudaFuncAttributeMaxDynamicSharedMemorySize, SMEM_BYTES);
    const int blocks = (n + 63) / 64;
    mlp_kernel<<<blocks, 512, SMEM_BYTES>>>(x, b0, b1, b2, (float*)d_out, n);
}